// round 12
// baseline (speedup 1.0000x reference)
#include <cuda_runtime.h>
#include <cuda_fp16.h>
#include <math.h>
#include <float.h>
#include <stdint.h>

#define S_LEN 2048
#define HID   2048
#define NHEAD 16
#define HS    128

// ---- scratch (no cudaMalloc allowed) ----
__device__ __half g_q[NHEAD * S_LEN * HS];
__device__ __half g_k[NHEAD * S_LEN * HS];
__device__ __half g_v[NHEAD * S_LEN * HS];
__device__ __half g_ctx[S_LEN * HID];
__device__ __half g_a[S_LEN * HID];            // hidden, fp16 [2048, 2048]
__device__ __half g_w_qkv[HID * 3 * HID];      // W_qkv fp16 [2048, 6144]
__device__ __half g_w_dense[HID * HID];        // W_dense fp16 [2048, 2048]

// m16n8k16 fp16 mma, fp32 accumulate
__device__ __forceinline__ void mma_f16(float* d, const uint32_t* a,
                                        const uint32_t* b, const float* c) {
    asm volatile(
        "mma.sync.aligned.m16n8k16.row.col.f32.f16.f16.f32 "
        "{%0, %1, %2, %3}, {%4, %5, %6, %7}, {%8, %9}, {%10, %11, %12, %13};"
        : "=f"(d[0]), "=f"(d[1]), "=f"(d[2]), "=f"(d[3])
        : "r"(a[0]), "r"(a[1]), "r"(a[2]), "r"(a[3]),
          "r"(b[0]), "r"(b[1]),
          "f"(c[0]), "f"(c[1]), "f"(c[2]), "f"(c[3]));
}

// m16n8k16 fp16 mma, fp16 accumulate (experiment: possibly double-rate)
__device__ __forceinline__ void mma_f16_h(uint32_t* d, const uint32_t* a,
                                          const uint32_t* b,
                                          uint32_t c0, uint32_t c1) {
    asm volatile(
        "mma.sync.aligned.m16n8k16.row.col.f16.f16.f16.f16 "
        "{%0, %1}, {%2, %3, %4, %5}, {%6, %7}, {%8, %9};"
        : "=r"(d[0]), "=r"(d[1])
        : "r"(a[0]), "r"(a[1]), "r"(a[2]), "r"(a[3]),
          "r"(b[0]), "r"(b[1]),
          "r"(c0), "r"(c1));
}

__device__ __forceinline__ void ldsm_x4(uint32_t* r, uint32_t addr) {
    asm volatile("ldmatrix.sync.aligned.m8n8.x4.shared.b16 {%0, %1, %2, %3}, [%4];"
                 : "=r"(r[0]), "=r"(r[1]), "=r"(r[2]), "=r"(r[3]) : "r"(addr));
}
__device__ __forceinline__ void ldsm_x4t(uint32_t* r, uint32_t addr) {
    asm volatile("ldmatrix.sync.aligned.m8n8.x4.trans.shared.b16 {%0, %1, %2, %3}, [%4];"
                 : "=r"(r[0]), "=r"(r[1]), "=r"(r[2]), "=r"(r[3]) : "r"(addr));
}
__device__ __forceinline__ void cp_async16(uint32_t smem, const void* g) {
    asm volatile("cp.async.cg.shared.global [%0], [%1], 16;"
                 :: "r"(smem), "l"(g) : "memory");
}

// =====================================================================
// prep: three branch-free fp32 -> fp16 converts
// WHICH: 0 = hidden -> g_a, 1 = W_qkv -> g_w_qkv, 2 = W_dense -> g_w_dense
// =====================================================================
template<int WHICH>
__global__ void __launch_bounds__(256) cvt_kernel(const float* __restrict__ src) {
    __half* dst = (WHICH == 0) ? g_a : (WHICH == 1) ? g_w_qkv : g_w_dense;
    size_t i = (size_t)blockIdx.x * 256 + threadIdx.x;   // 8-float group
    float4 v0 = ((const float4*)src)[2 * i];
    float4 v1 = ((const float4*)src)[2 * i + 1];
    __half2 h0 = __floats2half2_rn(v0.x, v0.y);
    __half2 h1 = __floats2half2_rn(v0.z, v0.w);
    __half2 h2 = __floats2half2_rn(v1.x, v1.y);
    __half2 h3 = __floats2half2_rn(v1.z, v1.w);
    uint4 packed = make_uint4(*(uint32_t*)&h0, *(uint32_t*)&h1,
                              *(uint32_t*)&h2, *(uint32_t*)&h3);
    *(uint4*)(dst + 8 * i) = packed;
}

// =====================================================================
// fp16 tensor GEMM: D[M,N] = A[M,K] @ W[K,N] + bias
// 4-stage cp.async pipeline + ldmatrix fragments.
// ACCH: 0 = fp32 accumulators (proven path)
//       1 = fp16 accumulators per 32-K chunk, flushed to fp32 each K-tile
// =====================================================================
#define ST2 40
#define BST 136
#define STAGES 4
#define A_STG (128 * ST2)
#define B_STG (32 * BST)
#define STG_HALFS (A_STG + B_STG)
#define GEMM_SMEM (STAGES * STG_HALFS * (int)sizeof(__half))

template<int MODE, int ACCH>
__global__ void __launch_bounds__(256)
tc_gemm(const float* __restrict__ bias, float* __restrict__ C, int K, int N)
{
    extern __shared__ __half smh[];

    const __half* A = (MODE == 0) ? g_a : g_ctx;
    const __half* B = (MODE == 0) ? g_w_qkv : g_w_dense;

    int tid  = threadIdx.x;
    int lane = tid & 31, wid = tid >> 5;
    int bcol = blockIdx.x * 128;
    int brow = blockIdx.y * 128;
    int wm = (wid >> 2) * 64;
    int wn = (wid & 3) * 32;

    int g = lane >> 2;
    int t = lane & 3;
    int lm = lane & 7;
    int lq = (lane >> 3) & 1;
    int lh = lane >> 4;

    float acc[4][4][4];
#pragma unroll
    for (int mt = 0; mt < 4; mt++)
#pragma unroll
        for (int nt = 0; nt < 4; nt++)
#pragma unroll
            for (int r = 0; r < 4; r++) acc[mt][nt][r] = 0.f;

    uint32_t a_lane = (uint32_t)((wm + lm + lq * 8) * ST2 + lh * 8);
    uint32_t b_lane = (uint32_t)((lm + lq * 8) * BST + wn + lh * 8);

    int sa_row = tid >> 2;
    int sa_c8  = (tid & 3) << 3;
    int sb_row = tid >> 3;
    int sb_c8  = (tid & 7) << 3;

    auto prefetch = [&](int kt, int s) {
        uint32_t base = (uint32_t)__cvta_generic_to_shared(smh + s * STG_HALFS);
#pragma unroll
        for (int it = 0; it < 2; it++) {
            int row = sa_row + it * 64;
            cp_async16(base + (uint32_t)(row * ST2 + sa_c8) * 2u,
                       A + (size_t)(brow + row) * K + kt * 32 + sa_c8);
        }
        const __half* bsrc = B + (size_t)(kt * 32 + sb_row) * N + bcol + sb_c8;
        uint32_t bdst = base + (uint32_t)(A_STG + sb_row * BST + sb_c8) * 2u;
        cp_async16(bdst,            bsrc);
        cp_async16(bdst + 64u * 2u, bsrc + 64);
        asm volatile("cp.async.commit_group;" ::: "memory");
    };

    const int NT = K / 32;
    prefetch(0, 0);
    prefetch(1, 1);
    prefetch(2, 2);

    for (int kt = 0; kt < NT; kt++) {
        asm volatile("cp.async.wait_group 2;" ::: "memory");
        __syncthreads();
        if (kt + 3 < NT) prefetch(kt + 3, (kt + 3) & 3);
        else asm volatile("cp.async.commit_group;" ::: "memory");

        uint32_t stage = (uint32_t)__cvta_generic_to_shared(
                             smh + (kt & 3) * STG_HALFS);
        uint32_t a_s = stage + a_lane * 2u;
        uint32_t b_s = stage + (uint32_t)A_STG * 2u + b_lane * 2u;

        // preload all B fragments for both K=16 halves (4 LDSM)
        uint32_t bf[2][4][2];
#pragma unroll
        for (int kk = 0; kk < 2; kk++)
#pragma unroll
            for (int np = 0; np < 2; np++) {
                uint32_t br[4];
                ldsm_x4t(br, b_s + (uint32_t)(kk * 16 * BST + np * 16) * 2u);
                bf[kk][2 * np][0]     = br[0];
                bf[kk][2 * np][1]     = br[1];
                bf[kk][2 * np + 1][0] = br[2];
                bf[kk][2 * np + 1][1] = br[3];
            }

        if (ACCH == 0) {
            // fp32-accumulate path (proven)
#pragma unroll
            for (int kk = 0; kk < 2; kk++)
#pragma unroll
                for (int mt = 0; mt < 4; mt++) {
                    uint32_t af[4];
                    ldsm_x4(af, a_s + (uint32_t)(mt * 16 * ST2 + kk * 16) * 2u);
#pragma unroll
                    for (int nt = 0; nt < 4; nt++)
                        mma_f16(acc[mt][nt], af, bf[kk][nt], acc[mt][nt]);
                }
        } else {
            // fp16-accumulate within this 32-K tile, flush to fp32
#pragma unroll
            for (int mt = 0; mt < 4; mt++) {
                uint32_t af0[4], af1[4];
                ldsm_x4(af0, a_s + (uint32_t)(mt * 16 * ST2) * 2u);
                ldsm_x4(af1, a_s + (uint32_t)(mt * 16 * ST2 + 16) * 2u);
                uint32_t h[4][2];
#pragma unroll
                for (int nt = 0; nt < 4; nt++)
                    mma_f16_h(h[nt], af0, bf[0][nt], 0u, 0u);
#pragma unroll
                for (int nt = 0; nt < 4; nt++)
                    mma_f16_h(h[nt], af1, bf[1][nt], h[nt][0], h[nt][1]);
#pragma unroll
                for (int nt = 0; nt < 4; nt++) {
                    float2 f0 = __half22float2(*(__half2*)&h[nt][0]);
                    float2 f1 = __half22float2(*(__half2*)&h[nt][1]);
                    acc[mt][nt][0] += f0.x;
                    acc[mt][nt][1] += f0.y;
                    acc[mt][nt][2] += f1.x;
                    acc[mt][nt][3] += f1.y;
                }
            }
        }
    }

    // ---- epilogue ----
    if (MODE == 0) {
        int kind = bcol >> 11;
        int head = (bcol & 2047) >> 7;
        __half* dstbase = (kind == 0 ? g_q : kind == 1 ? g_k : g_v)
                          + (size_t)head * S_LEN * HS;
#pragma unroll
        for (int mt = 0; mt < 4; mt++) {
#pragma unroll
            for (int nt = 0; nt < 4; nt++) {
                int col = wn + nt * 8 + 2 * t;
                int bi  = bcol + col;
                float bx = __ldg(&bias[bi]), by = __ldg(&bias[bi + 1]);
                int r0 = brow + wm + mt * 16 + g;
                __half2 v0 = __floats2half2_rn(acc[mt][nt][0] + bx, acc[mt][nt][1] + by);
                __half2 v1 = __floats2half2_rn(acc[mt][nt][2] + bx, acc[mt][nt][3] + by);
                *(__half2*)(dstbase + (size_t)r0 * HS + col)       = v0;
                *(__half2*)(dstbase + (size_t)(r0 + 8) * HS + col) = v1;
            }
        }
    } else {
#pragma unroll
        for (int mt = 0; mt < 4; mt++) {
#pragma unroll
            for (int nt = 0; nt < 4; nt++) {
                int col = bcol + wn + nt * 8 + 2 * t;
                float bx = __ldg(&bias[col]), by = __ldg(&bias[col + 1]);
                int r0 = brow + wm + mt * 16 + g;
                float2 v0 = make_float2(acc[mt][nt][0] + bx, acc[mt][nt][1] + by);
                float2 v1 = make_float2(acc[mt][nt][2] + bx, acc[mt][nt][3] + by);
                *(float2*)(C + (size_t)r0 * N + col)       = v0;
                *(float2*)(C + (size_t)(r0 + 8) * N + col) = v1;
            }
        }
    }
}

// =====================================================================
// fp16 flash attention: P-in-registers + cp.async double-buffered K/V.
// (verbatim from R11 passing version)
// =====================================================================
#define QS2 136
#define KV_STG (64 * QS2)

__global__ void __launch_bounds__(256) attn_kernel()
{
    extern __shared__ __half smha[];
    __half* Qs = smha;

    int tid  = threadIdx.x;
    int lane = tid & 31, wid = tid >> 5;
    int g = lane >> 2, t = lane & 3;
    int lm = lane & 7;
    int lq = (lane >> 3) & 1;
    int lh = lane >> 4;

    int qtile = (gridDim.x - 1) - blockIdx.x;
    int head  = blockIdx.y;
    const __half* Qp = g_q + (size_t)head * S_LEN * HS;
    const __half* Kp = g_k + (size_t)head * S_LEN * HS;
    const __half* Vp = g_v + (size_t)head * S_LEN * HS;

    int q0 = qtile * 128;

#pragma unroll
    for (int it = 0; it < 8; it++) {
        int idx = tid + it * 256;
        int r  = idx >> 4;
        int c8 = (idx & 15) << 3;
        *(uint4*)&Qs[r * QS2 + c8] = *(const uint4*)(Qp + (size_t)(q0 + r) * HS + c8);
    }

    const float scale = 0.08838834764831845f;
    int lr   = wid * 16 + g;
    int row0 = q0 + lr;

    uint32_t smbase = (uint32_t)__cvta_generic_to_shared(smha);
    uint32_t qs_base = smbase
                     + (uint32_t)((wid * 16 + lm + lq * 8) * QS2 + lh * 8) * 2u;
    uint32_t kv0 = smbase + (uint32_t)(128 * QS2) * 2u;
    uint32_t ks_lane = (uint32_t)((lm + lh * 8) * QS2 + lq * 8) * 2u;
    uint32_t vs_lane = (uint32_t)((lm + lq * 8) * QS2 + lh * 8) * 2u;

    int p_r  = tid >> 4;
    int p_c8 = (tid & 15) << 3;

    auto prefetch_kv = [&](int jt_, int buf) {
        uint32_t kb = kv0 + (uint32_t)(buf * 2 * KV_STG) * 2u;
        uint32_t vb = kb + (uint32_t)KV_STG * 2u;
        int k0_ = jt_ * 64;
#pragma unroll
        for (int it = 0; it < 4; it++) {
            int row = p_r + it * 16;
            uint32_t so = (uint32_t)(row * QS2 + p_c8) * 2u;
            cp_async16(kb + so, Kp + (size_t)(k0_ + row) * HS + p_c8);
            cp_async16(vb + so, Vp + (size_t)(k0_ + row) * HS + p_c8);
        }
    };

    float m0 = -FLT_MAX, m1 = -FLT_MAX, l0 = 0.f, l1 = 0.f;
    float o[16][4];
#pragma unroll
    for (int nt = 0; nt < 16; nt++)
#pragma unroll
        for (int r = 0; r < 4; r++) o[nt][r] = 0.f;

    int jmax = 2 * qtile + 1;
    prefetch_kv(0, 0);
    asm volatile("cp.async.commit_group;" ::: "memory");

    for (int jt = 0; jt <= jmax; jt++) {
        int k0 = jt * 64;
        int buf = jt & 1;
        __syncthreads();
        if (jt < jmax) prefetch_kv(jt + 1, buf ^ 1);
        asm volatile("cp.async.commit_group;" ::: "memory");
        asm volatile("cp.async.wait_group 1;" ::: "memory");
        __syncthreads();

        uint32_t ks_base = kv0 + (uint32_t)(buf * 2 * KV_STG) * 2u + ks_lane;
        uint32_t vs_base = kv0 + (uint32_t)(buf * 2 * KV_STG + KV_STG) * 2u + vs_lane;

        float sacc[8][4];
#pragma unroll
        for (int nt = 0; nt < 8; nt++)
#pragma unroll
            for (int r = 0; r < 4; r++) sacc[nt][r] = 0.f;

#pragma unroll
        for (int kk = 0; kk < 8; kk++) {
            uint32_t af[4];
            ldsm_x4(af, qs_base + (uint32_t)(kk * 16) * 2u);
#pragma unroll
            for (int np = 0; np < 4; np++) {
                uint32_t br[4];
                ldsm_x4(br, ks_base + (uint32_t)(np * 16 * QS2 + kk * 16) * 2u);
                mma_f16(sacc[2 * np],     af, &br[0], sacc[2 * np]);
                mma_f16(sacc[2 * np + 1], af, &br[2], sacc[2 * np + 1]);
            }
        }

        bool diag = (jt >= 2 * qtile);
        float mx0 = -FLT_MAX, mx1 = -FLT_MAX;
#pragma unroll
        for (int nt = 0; nt < 8; nt++) {
            int colb = k0 + nt * 8 + 2 * t;
            float v0 = sacc[nt][0] * scale;
            float v1 = sacc[nt][1] * scale;
            float v2 = sacc[nt][2] * scale;
            float v3 = sacc[nt][3] * scale;
            if (diag) {
                if (colb     > row0)     v0 = -FLT_MAX;
                if (colb + 1 > row0)     v1 = -FLT_MAX;
                if (colb     > row0 + 8) v2 = -FLT_MAX;
                if (colb + 1 > row0 + 8) v3 = -FLT_MAX;
            }
            sacc[nt][0] = v0; sacc[nt][1] = v1;
            sacc[nt][2] = v2; sacc[nt][3] = v3;
            mx0 = fmaxf(mx0, fmaxf(v0, v1));
            mx1 = fmaxf(mx1, fmaxf(v2, v3));
        }
        mx0 = fmaxf(mx0, __shfl_xor_sync(0xffffffffu, mx0, 1));
        mx0 = fmaxf(mx0, __shfl_xor_sync(0xffffffffu, mx0, 2));
        mx1 = fmaxf(mx1, __shfl_xor_sync(0xffffffffu, mx1, 1));
        mx1 = fmaxf(mx1, __shfl_xor_sync(0xffffffffu, mx1, 2));
        float m0n = fmaxf(m0, mx0), m1n = fmaxf(m1, mx1);

        uint32_t paf[4][4];
        float s0 = 0.f, s1 = 0.f;
#pragma unroll
        for (int kk = 0; kk < 4; kk++) {
#pragma unroll
            for (int h = 0; h < 2; h++) {
                int nt = 2 * kk + h;
                float p0 = __expf(sacc[nt][0] - m0n);
                float p1 = __expf(sacc[nt][1] - m0n);
                float p2 = __expf(sacc[nt][2] - m1n);
                float p3 = __expf(sacc[nt][3] - m1n);
                s0 += p0 + p1;
                s1 += p2 + p3;
                __half2 lo = __floats2half2_rn(p0, p1);
                __half2 hi = __floats2half2_rn(p2, p3);
                paf[kk][2 * h]     = *(uint32_t*)&lo;
                paf[kk][2 * h + 1] = *(uint32_t*)&hi;
            }
        }
        s0 += __shfl_xor_sync(0xffffffffu, s0, 1);
        s0 += __shfl_xor_sync(0xffffffffu, s0, 2);
        s1 += __shfl_xor_sync(0xffffffffu, s1, 1);
        s1 += __shfl_xor_sync(0xffffffffu, s1, 2);

        float sc0 = __expf(m0 - m0n), sc1 = __expf(m1 - m1n);
        l0 = l0 * sc0 + s0;  l1 = l1 * sc1 + s1;
        m0 = m0n;            m1 = m1n;
#pragma unroll
        for (int nt = 0; nt < 16; nt++) {
            o[nt][0] *= sc0; o[nt][1] *= sc0;
            o[nt][2] *= sc1; o[nt][3] *= sc1;
        }

#pragma unroll
        for (int kk = 0; kk < 4; kk++) {
#pragma unroll
            for (int np = 0; np < 8; np++) {
                uint32_t br[4];
                ldsm_x4t(br, vs_base + (uint32_t)(kk * 16 * QS2 + np * 16) * 2u);
                mma_f16(o[2 * np],     paf[kk], &br[0], o[2 * np]);
                mma_f16(o[2 * np + 1], paf[kk], &br[2], o[2 * np + 1]);
            }
        }
    }

    float inv0 = 1.f / l0, inv1 = 1.f / l1;
    __half* dst0 = g_ctx + (size_t)row0 * HID + head * HS;
    __half* dst1 = dst0 + (size_t)8 * HID;
#pragma unroll
    for (int nt = 0; nt < 16; nt++) {
        int c = nt * 8 + 2 * t;
        *(__half2*)(dst0 + c) = __floats2half2_rn(o[nt][0] * inv0, o[nt][1] * inv0);
        *(__half2*)(dst1 + c) = __floats2half2_rn(o[nt][2] * inv1, o[nt][3] * inv1);
    }
}

// =====================================================================
// launch
// =====================================================================
extern "C" void kernel_launch(void* const* d_in, const int* in_sizes, int n_in,
                              void* d_out, int out_size)
{
    const float* hidden  = (const float*)d_in[0];
    // d_in[1] = ltor_mask (always causal tril; handled analytically)
    const float* W_qkv   = (const float*)d_in[2];
    const float* b_qkv   = (const float*)d_in[3];
    const float* W_dense = (const float*)d_in[4];
    const float* b_dense = (const float*)d_in[5];
    float* out = (float*)d_out;

    const int ATTN_SMEM = (128 * QS2 + 4 * KV_STG) * (int)sizeof(__half);
    cudaFuncSetAttribute(attn_kernel,
                         cudaFuncAttributeMaxDynamicSharedMemorySize, ATTN_SMEM);
    cudaFuncSetAttribute(tc_gemm<0, 0>,
                         cudaFuncAttributeMaxDynamicSharedMemorySize, GEMM_SMEM);
    cudaFuncSetAttribute(tc_gemm<1, 1>,
                         cudaFuncAttributeMaxDynamicSharedMemorySize, GEMM_SMEM);

    // prep: branch-free fp32 -> fp16 converts
    cvt_kernel<0><<<(S_LEN * HID / 8) / 256, 256>>>(hidden);
    cvt_kernel<1><<<(HID * 3 * HID / 8) / 256, 256>>>(W_qkv);
    cvt_kernel<2><<<(HID * HID / 8) / 256, 256>>>(W_dense);

    // 1) QKV projection (fp32-accum, proven)
    tc_gemm<0, 0><<<dim3(3 * HID / 128, S_LEN / 128), 256, GEMM_SMEM>>>(b_qkv, nullptr,
                                                                        HID, 3 * HID);
    // 2) causal flash attention -> g_ctx
    attn_kernel<<<dim3(16, 16), 256, ATTN_SMEM>>>();

    // 3) dense projection (fp16-accum experiment, chunked K=32 -> fp32)
    tc_gemm<1, 1><<<dim3(HID / 128, S_LEN / 128), 256, GEMM_SMEM>>>(b_dense, out,
                                                                    HID, HID);
}